// round 10
// baseline (speedup 1.0000x reference)
#include <cuda_runtime.h>
#include <math.h>

#define BB   4
#define TT   2048
#define DD   1024
#define HH   16
#define DHD  64
#define MM   (BB * TT)        /* 8192 */
#define N3   (3 * DD)         /* 3072 */
#define NBH  (BB * HH)        /* 64   */

// ---------------------------------------------------------------------------
// Scratch (device globals; no dynamic allocation allowed)
// ---------------------------------------------------------------------------
__device__ float g_QKV[(size_t)MM * N3];          // [m][3072]
__device__ float g_Qt [(size_t)NBH * DHD * TT];   // [bh][d][t]
__device__ float g_Kt [(size_t)NBH * DHD * TT];   // [bh][d][t]
__device__ float g_V  [(size_t)NBH * TT * DHD];   // [bh][t][d]
__device__ float g_A  [(size_t)MM * DD];          // attn out, [m][n]
__device__ float g_cos[TT * 32];
__device__ float g_sin[TT * 32];

// ---------------------------------------------------------------------------
// f32x2 packed-FMA helpers (Blackwell FFMA2: 2x fp32 throughput)
// ---------------------------------------------------------------------------
typedef unsigned long long u64;

__device__ __forceinline__ u64 pack2(float x, float y) {
    u64 r;
    asm("mov.b64 %0, {%1, %2};" : "=l"(r) : "f"(x), "f"(y));
    return r;
}
__device__ __forceinline__ float2 unpack2(u64 v) {
    float2 r;
    asm("mov.b64 {%0, %1}, %2;" : "=f"(r.x), "=f"(r.y) : "l"(v));
    return r;
}
__device__ __forceinline__ u64 fma2(u64 a, u64 b, u64 c) {
    u64 d;
    asm("fma.rn.f32x2 %0, %1, %2, %3;" : "=l"(d) : "l"(a), "l"(b), "l"(c));
    return d;
}
__device__ __forceinline__ u64 mul2(u64 a, u64 b) {
    u64 d;
    asm("mul.rn.f32x2 %0, %1, %2;" : "=l"(d) : "l"(a), "l"(b));
    return d;
}

// ---------------------------------------------------------------------------
// Kernel 1: RoPE cos/sin table. Accurate sincos of the f32-rounded angle
// (matches reference rounding chain; __sinf would be garbage at ~2000 rad).
// ---------------------------------------------------------------------------
__global__ void rope_table_kernel() {
    int idx = blockIdx.x * blockDim.x + threadIdx.x;   // t*32 + i
    if (idx >= TT * 32) return;
    int t = idx >> 5, i = idx & 31;
    float inv = (float)pow(10000.0, -(double)i / 32.0);
    float ang = (float)t * inv;                        // f32 product like reference
    double s, c;
    sincos((double)ang, &s, &c);
    g_cos[idx] = (float)c;
    g_sin[idx] = (float)s;
}

// ---------------------------------------------------------------------------
// Kernel 2/5: GEMM  C[M][N] = A[M][1024] @ W[N][1024]^T + bias[N]
// 64x64 tile, K-step 16, 256 threads, 4x4 per thread, f32x2 accumulators.
// Bs stored [k][n] so the n-pairs load as aligned float2 directly.
// ---------------------------------------------------------------------------
__global__ __launch_bounds__(256) void gemm_bias_kernel(
    const float* __restrict__ A, const float* __restrict__ W,
    const float* __restrict__ bias, float* __restrict__ C, int N)
{
    __shared__ float As[64][17];   // [m][k], pad 17 -> 2-way max on reads
    __shared__ float Bs[16][64];   // [k][n]

    const int tid = threadIdx.x;
    const int tx = tid & 15, ty = tid >> 4;
    const int m0 = blockIdx.y * 64;
    const int n0 = blockIdx.x * 64;

    const int lr = tid >> 2;            // 0..63 (row for loads)
    const int lk = (tid & 3) * 4;       // 0..12 (k-quad for loads)

    u64 acc[4][2];
    #pragma unroll
    for (int r = 0; r < 4; r++) { acc[r][0] = pack2(0.f, 0.f); acc[r][1] = pack2(0.f, 0.f); }

    for (int kt = 0; kt < 1024; kt += 16) {
        // load A tile (coalesced float4), store [m][k]
        float4 av = *(const float4*)&A[(size_t)(m0 + lr) * 1024 + kt + lk];
        As[lr][lk + 0] = av.x; As[lr][lk + 1] = av.y;
        As[lr][lk + 2] = av.z; As[lr][lk + 3] = av.w;
        // load W tile (coalesced float4), store transposed [k][n]
        float4 bv = *(const float4*)&W[(size_t)(n0 + lr) * 1024 + kt + lk];
        Bs[lk + 0][lr] = bv.x; Bs[lk + 1][lr] = bv.y;
        Bs[lk + 2][lr] = bv.z; Bs[lk + 3][lr] = bv.w;
        __syncthreads();

        #pragma unroll
        for (int kk = 0; kk < 16; kk++) {
            u64 b01 = *(const u64*)&Bs[kk][4 * tx];
            u64 b23 = *(const u64*)&Bs[kk][4 * tx + 2];
            #pragma unroll
            for (int r = 0; r < 4; r++) {
                float a = As[4 * ty + r][kk];
                u64 a2 = pack2(a, a);
                acc[r][0] = fma2(a2, b01, acc[r][0]);
                acc[r][1] = fma2(a2, b23, acc[r][1]);
            }
        }
        __syncthreads();
    }

    float4 bv = *(const float4*)&bias[n0 + 4 * tx];
    #pragma unroll
    for (int r = 0; r < 4; r++) {
        float2 u0 = unpack2(acc[r][0]);
        float2 u1 = unpack2(acc[r][1]);
        float4 res = make_float4(u0.x + bv.x, u0.y + bv.y, u1.x + bv.z, u1.y + bv.w);
        *(float4*)&C[(size_t)(m0 + 4 * ty + r) * N + n0 + 4 * tx] = res;
    }
}

// ---------------------------------------------------------------------------
// Kernel 3: RoPE + scatter. Reads g_QKV, writes Q,K transposed [bh][d][t]
// (so attention tile loads are linear) and V as [bh][t][d].
// One thread per (m, h, pair-i).
// ---------------------------------------------------------------------------
__global__ __launch_bounds__(256) void rope_scatter_kernel() {
    int idx = blockIdx.x * 256 + threadIdx.x;   // [0, MM*512)
    int m = idx >> 9;
    int p = idx & 511;
    int h = p >> 5, i = p & 31;
    int b = m >> 11, t = m & 2047;

    const float* base = g_QKV + (size_t)m * N3;
    float2 q = *(const float2*)&base[h * 64 + 2 * i];
    float2 k = *(const float2*)&base[1024 + h * 64 + 2 * i];
    float2 v = *(const float2*)&base[2048 + h * 64 + 2 * i];

    float c = g_cos[t * 32 + i];
    float s = g_sin[t * 32 + i];

    float qr0 = q.x * c - q.y * s, qr1 = q.x * s + q.y * c;
    float kr0 = k.x * c - k.y * s, kr1 = k.x * s + k.y * c;

    int bh = b * 16 + h;
    size_t toff = ((size_t)bh * 64 + 2 * i) * 2048 + t;
    g_Qt[toff]        = qr0;
    g_Qt[toff + 2048] = qr1;
    g_Kt[toff]        = kr0;
    g_Kt[toff + 2048] = kr1;

    *(float2*)&g_V[((size_t)bh * 2048 + t) * 64 + 2 * i] = v;
}

// ---------------------------------------------------------------------------
// Kernel 4: flash attention. grid(32 q-tiles, 64 bh), 256 threads.
// Tiles 64q x 64kv, 4x4 per thread, online softmax, f32x2 FMAs.
// ---------------------------------------------------------------------------
#define ATTN_SMEM ((4096 * 3 + 64 * 65) * 4)   /* 65792 B */

__global__ __launch_bounds__(256) void attn_kernel() {
    extern __shared__ float sm[];
    float* Qs = sm;             // [d][q]  64x64
    float* Ks = sm + 4096;      // [d][k]  64x64
    float* Vs = sm + 8192;      // [k][d]  64x64
    float* Ps = sm + 12288;     // [q][k]  64x65

    const int bh = blockIdx.y;
    const int q0 = blockIdx.x * 64;
    const int tid = threadIdx.x;
    const int tx = tid & 15, ty = tid >> 4;

    const float* Qb = g_Qt + (size_t)bh * 64 * 2048;
    const float* Kb = g_Kt + (size_t)bh * 64 * 2048;
    const float* Vb = g_V  + (size_t)bh * 2048 * 64;

    // load Q tile [d][q] (linear copy thanks to [bh][d][t] layout)
    #pragma unroll
    for (int it = 0; it < 4; it++) {
        int idx = tid + it * 256;          // float4 index, 0..1023
        int d = idx >> 4, qq = (idx & 15) * 4;
        *(float4*)&Qs[d * 64 + qq] = *(const float4*)&Qb[(size_t)d * 2048 + q0 + qq];
    }

    float m_i[4], l_i[4];
    u64 o2[4][2];
    #pragma unroll
    for (int r = 0; r < 4; r++) {
        m_i[r] = -1e30f; l_i[r] = 0.f;
        o2[r][0] = pack2(0.f, 0.f); o2[r][1] = pack2(0.f, 0.f);
    }

    const float scale = 0.125f;   // 1/sqrt(64)

    for (int kt = 0; kt < 32; kt++) {
        __syncthreads();   // prev PV + P reads done before overwrite
        // load K tile [d][k] and V tile [k][d] (both linear copies)
        #pragma unroll
        for (int it = 0; it < 4; it++) {
            int idx = tid + it * 256;
            int d = idx >> 4, kq = (idx & 15) * 4;
            *(float4*)&Ks[d * 64 + kq] =
                *(const float4*)&Kb[(size_t)d * 2048 + kt * 64 + kq];
            *(float4*)&Vs[idx * 4] =
                *(const float4*)&Vb[(size_t)kt * 64 * 64 + idx * 4];
        }
        __syncthreads();

        // S = Q^T K  (over d)
        u64 s2[4][2];
        #pragma unroll
        for (int r = 0; r < 4; r++) { s2[r][0] = pack2(0.f, 0.f); s2[r][1] = pack2(0.f, 0.f); }

        #pragma unroll 4
        for (int d = 0; d < 64; d++) {
            float4 q4 = *(const float4*)&Qs[d * 64 + 4 * ty];
            u64 k01 = *(const u64*)&Ks[d * 64 + 4 * tx];
            u64 k23 = *(const u64*)&Ks[d * 64 + 4 * tx + 2];
            u64 a0 = pack2(q4.x, q4.x);
            u64 a1 = pack2(q4.y, q4.y);
            u64 a2 = pack2(q4.z, q4.z);
            u64 a3 = pack2(q4.w, q4.w);
            s2[0][0] = fma2(a0, k01, s2[0][0]); s2[0][1] = fma2(a0, k23, s2[0][1]);
            s2[1][0] = fma2(a1, k01, s2[1][0]); s2[1][1] = fma2(a1, k23, s2[1][1]);
            s2[2][0] = fma2(a2, k01, s2[2][0]); s2[2][1] = fma2(a2, k23, s2[2][1]);
            s2[3][0] = fma2(a3, k01, s2[3][0]); s2[3][1] = fma2(a3, k23, s2[3][1]);
        }

        // online softmax per row (rows owned across the 16 tx lanes)
        #pragma unroll
        for (int r = 0; r < 4; r++) {
            float2 u0 = unpack2(s2[r][0]);
            float2 u1 = unpack2(s2[r][1]);
            float sv[4];
            sv[0] = u0.x * scale; sv[1] = u0.y * scale;
            sv[2] = u1.x * scale; sv[3] = u1.y * scale;

            float mx = fmaxf(fmaxf(sv[0], sv[1]), fmaxf(sv[2], sv[3]));
            #pragma unroll
            for (int off = 1; off < 16; off <<= 1)
                mx = fmaxf(mx, __shfl_xor_sync(0xffffffffu, mx, off));

            float mnew = fmaxf(m_i[r], mx);
            float alpha = __expf(m_i[r] - mnew);
            float rsum = 0.f;
            #pragma unroll
            for (int c = 0; c < 4; c++) {
                sv[c] = __expf(sv[c] - mnew);
                rsum += sv[c];
            }
            #pragma unroll
            for (int off = 1; off < 16; off <<= 1)
                rsum += __shfl_xor_sync(0xffffffffu, rsum, off);

            l_i[r] = l_i[r] * alpha + rsum;
            m_i[r] = mnew;
            u64 al2 = pack2(alpha, alpha);
            o2[r][0] = mul2(o2[r][0], al2);
            o2[r][1] = mul2(o2[r][1], al2);

            // P tile, pitch 65 (scalar stores; pitch keeps reads 2-way max)
            float* prow = &Ps[(4 * ty + r) * 65 + 4 * tx];
            prow[0] = sv[0]; prow[1] = sv[1]; prow[2] = sv[2]; prow[3] = sv[3];
        }
        __syncthreads();

        // O += P V
        #pragma unroll 4
        for (int k = 0; k < 64; k++) {
            u64 v01 = *(const u64*)&Vs[k * 64 + 4 * tx];
            u64 v23 = *(const u64*)&Vs[k * 64 + 4 * tx + 2];
            #pragma unroll
            for (int r = 0; r < 4; r++) {
                float p = Ps[(4 * ty + r) * 65 + k];
                u64 p2 = pack2(p, p);
                o2[r][0] = fma2(p2, v01, o2[r][0]);
                o2[r][1] = fma2(p2, v23, o2[r][1]);
            }
        }
    }

    // epilogue: O /= l, write to g_A[b*T+t][h*64+d]
    const int b = bh >> 4, h = bh & 15;
    #pragma unroll
    for (int r = 0; r < 4; r++) {
        float inv = 1.0f / l_i[r];
        float2 u0 = unpack2(o2[r][0]);
        float2 u1 = unpack2(o2[r][1]);
        float4 res = make_float4(u0.x * inv, u0.y * inv, u1.x * inv, u1.y * inv);
        size_t off = ((size_t)(b * 2048 + q0 + 4 * ty + r)) * 1024 + h * 64 + 4 * tx;
        *(float4*)&g_A[off] = res;
    }
}

// ---------------------------------------------------------------------------
// Launcher
// ---------------------------------------------------------------------------
extern "C" void kernel_launch(void* const* d_in, const int* in_sizes, int n_in,
                              void* d_out, int out_size) {
    (void)in_sizes; (void)n_in; (void)out_size;
    const float* query = (const float*)d_in[0];
    const float* w_in  = (const float*)d_in[1];
    const float* b_in  = (const float*)d_in[2];
    const float* w_out = (const float*)d_in[3];
    const float* b_out = (const float*)d_in[4];
    float* out = (float*)d_out;

    void* pQKV = nullptr; void* pA = nullptr;
    cudaGetSymbolAddress(&pQKV, g_QKV);
    cudaGetSymbolAddress(&pA,   g_A);
    cudaFuncSetAttribute(attn_kernel,
                         cudaFuncAttributeMaxDynamicSharedMemorySize, ATTN_SMEM);

    rope_table_kernel<<<(TT * 32 + 255) / 256, 256>>>();

    gemm_bias_kernel<<<dim3(N3 / 64, MM / 64), 256>>>(
        query, w_in, b_in, (float*)pQKV, N3);

    rope_scatter_kernel<<<(MM * 512) / 256, 256>>>();

    attn_kernel<<<dim3(TT / 64, NBH), 256, ATTN_SMEM>>>();

    gemm_bias_kernel<<<dim3(DD / 64, MM / 64), 256>>>(
        (const float*)pA, w_out, b_out, out, DD);
}

// round 11
// speedup vs baseline: 1.2294x; 1.2294x over previous
#include <cuda_runtime.h>
#include <math.h>

#define BB   4
#define TT   2048
#define DD   1024
#define HH   16
#define DHD  64
#define MM   (BB * TT)        /* 8192 */
#define N3   (3 * DD)         /* 3072 */
#define NBH  (BB * HH)        /* 64   */

// ---------------------------------------------------------------------------
// Scratch (device globals; no dynamic allocation allowed)
// ---------------------------------------------------------------------------
__device__ float g_QKV[(size_t)MM * N3];          // [m][3072]
__device__ float g_Qt [(size_t)NBH * DHD * TT];   // [bh][d][t]
__device__ float g_Kt [(size_t)NBH * DHD * TT];   // [bh][d][t]
__device__ float g_V  [(size_t)NBH * TT * DHD];   // [bh][t][d]
__device__ float g_A  [(size_t)MM * DD];          // attn out, [m][n]
__device__ float g_cos[TT * 32];
__device__ float g_sin[TT * 32];

// ---------------------------------------------------------------------------
// f32x2 packed-FMA helpers (Blackwell FFMA2: 2x fp32 throughput)
// ---------------------------------------------------------------------------
typedef unsigned long long u64;

__device__ __forceinline__ u64 pack2(float x, float y) {
    u64 r;
    asm("mov.b64 %0, {%1, %2};" : "=l"(r) : "f"(x), "f"(y));
    return r;
}
__device__ __forceinline__ float2 unpack2(u64 v) {
    float2 r;
    asm("mov.b64 {%0, %1}, %2;" : "=f"(r.x), "=f"(r.y) : "l"(v));
    return r;
}
__device__ __forceinline__ u64 fma2(u64 a, u64 b, u64 c) {
    u64 d;
    asm("fma.rn.f32x2 %0, %1, %2, %3;" : "=l"(d) : "l"(a), "l"(b), "l"(c));
    return d;
}
__device__ __forceinline__ u64 mul2(u64 a, u64 b) {
    u64 d;
    asm("mul.rn.f32x2 %0, %1, %2;" : "=l"(d) : "l"(a), "l"(b));
    return d;
}

// ---------------------------------------------------------------------------
// Kernel 1: RoPE cos/sin table (accurate sincos of the f32-rounded angle).
// ---------------------------------------------------------------------------
__global__ void rope_table_kernel() {
    int idx = blockIdx.x * blockDim.x + threadIdx.x;   // t*32 + i
    if (idx >= TT * 32) return;
    int t = idx >> 5, i = idx & 31;
    float inv = (float)pow(10000.0, -(double)i / 32.0);
    float ang = (float)t * inv;                        // f32 product like reference
    double s, c;
    sincos((double)ang, &s, &c);
    g_cos[idx] = (float)c;
    g_sin[idx] = (float)s;
}

// ---------------------------------------------------------------------------
// Kernel 2/5: GEMM  C[M][N] = A[M][1024] @ W[N][1024]^T + bias[N]
// 128x128 tile, K-step 16, 256 threads, 8x8 per thread.
// As stored [k][m] (transposed), Bs [k][n]: A operand loads as u64 pairs
// (accumulators paired along m, zero packs on A); B broadcast-packed.
// gmem->reg prefetch hides L2 latency across the sync.
// ---------------------------------------------------------------------------
__global__ __launch_bounds__(256, 2) void gemm_bias_kernel(
    const float* __restrict__ A, const float* __restrict__ W,
    const float* __restrict__ bias, float* __restrict__ C, int N)
{
    __shared__ float As[16][128];   // [k][m]
    __shared__ float Bs[16][128];   // [k][n]

    const int tid = threadIdx.x;
    const int tx = tid & 15;          // n: 8*tx
    const int ty = tid >> 4;          // m: 8*ty
    const int m0 = blockIdx.y * 128;
    const int n0 = blockIdx.x * 128;

    const int lr = tid >> 1;          // 0..127
    const int lk = (tid & 1) * 8;     // 0 or 8

    const float* Aptr = A + (size_t)(m0 + lr) * 1024 + lk;
    const float* Wptr = W + (size_t)(n0 + lr) * 1024 + lk;

    u64 acc[4][8];
    #pragma unroll
    for (int mp = 0; mp < 4; mp++)
        #pragma unroll
        for (int n = 0; n < 8; n++) acc[mp][n] = 0ULL;

    // prefetch first k-tile
    float4 a0 = *(const float4*)(Aptr);
    float4 a1 = *(const float4*)(Aptr + 4);
    float4 w0 = *(const float4*)(Wptr);
    float4 w1 = *(const float4*)(Wptr + 4);

    for (int kt = 0; kt < 1024; kt += 16) {
        // store prefetched tile (scatter to [k][m] / [k][n]; 2-way max)
        As[lk + 0][lr] = a0.x; As[lk + 1][lr] = a0.y;
        As[lk + 2][lr] = a0.z; As[lk + 3][lr] = a0.w;
        As[lk + 4][lr] = a1.x; As[lk + 5][lr] = a1.y;
        As[lk + 6][lr] = a1.z; As[lk + 7][lr] = a1.w;
        Bs[lk + 0][lr] = w0.x; Bs[lk + 1][lr] = w0.y;
        Bs[lk + 2][lr] = w0.z; Bs[lk + 3][lr] = w0.w;
        Bs[lk + 4][lr] = w1.x; Bs[lk + 5][lr] = w1.y;
        Bs[lk + 6][lr] = w1.z; Bs[lk + 7][lr] = w1.w;
        __syncthreads();

        if (kt + 16 < 1024) {   // prefetch next tile (overlaps compute)
            a0 = *(const float4*)(Aptr + kt + 16);
            a1 = *(const float4*)(Aptr + kt + 20);
            w0 = *(const float4*)(Wptr + kt + 16);
            w1 = *(const float4*)(Wptr + kt + 20);
        }

        #pragma unroll
        for (int kk = 0; kk < 16; kk++) {
            const float* arow = &As[kk][8 * ty];
            u64 am0 = *(const u64*)(arow);
            u64 am1 = *(const u64*)(arow + 2);
            u64 am2 = *(const u64*)(arow + 4);
            u64 am3 = *(const u64*)(arow + 6);
            float4 b0 = *(const float4*)&Bs[kk][8 * tx];
            float4 b1 = *(const float4*)&Bs[kk][8 * tx + 4];
            u64 bb[8];
            bb[0] = pack2(b0.x, b0.x); bb[1] = pack2(b0.y, b0.y);
            bb[2] = pack2(b0.z, b0.z); bb[3] = pack2(b0.w, b0.w);
            bb[4] = pack2(b1.x, b1.x); bb[5] = pack2(b1.y, b1.y);
            bb[6] = pack2(b1.z, b1.z); bb[7] = pack2(b1.w, b1.w);
            #pragma unroll
            for (int n = 0; n < 8; n++) {
                acc[0][n] = fma2(am0, bb[n], acc[0][n]);
                acc[1][n] = fma2(am1, bb[n], acc[1][n]);
                acc[2][n] = fma2(am2, bb[n], acc[2][n]);
                acc[3][n] = fma2(am3, bb[n], acc[3][n]);
            }
        }
        __syncthreads();
    }

    float4 bv0 = *(const float4*)&bias[n0 + 8 * tx];
    float4 bv1 = *(const float4*)&bias[n0 + 8 * tx + 4];
    #pragma unroll
    for (int mp = 0; mp < 4; mp++) {
        float r0[8], r1[8];
        #pragma unroll
        for (int n = 0; n < 8; n++) {
            float2 u = unpack2(acc[mp][n]);
            r0[n] = u.x; r1[n] = u.y;
        }
        size_t row0 = (size_t)(m0 + 8 * ty + 2 * mp) * N + n0 + 8 * tx;
        *(float4*)&C[row0]     = make_float4(r0[0]+bv0.x, r0[1]+bv0.y, r0[2]+bv0.z, r0[3]+bv0.w);
        *(float4*)&C[row0 + 4] = make_float4(r0[4]+bv1.x, r0[5]+bv1.y, r0[6]+bv1.z, r0[7]+bv1.w);
        size_t row1 = row0 + N;
        *(float4*)&C[row1]     = make_float4(r1[0]+bv0.x, r1[1]+bv0.y, r1[2]+bv0.z, r1[3]+bv0.w);
        *(float4*)&C[row1 + 4] = make_float4(r1[4]+bv1.x, r1[5]+bv1.y, r1[6]+bv1.z, r1[7]+bv1.w);
    }
}

// ---------------------------------------------------------------------------
// Kernel 3: RoPE + scatter. Writes Q,K transposed [bh][d][t], V as [bh][t][d].
// ---------------------------------------------------------------------------
__global__ __launch_bounds__(256) void rope_scatter_kernel() {
    int idx = blockIdx.x * 256 + threadIdx.x;   // [0, MM*512)
    int m = idx >> 9;
    int p = idx & 511;
    int h = p >> 5, i = p & 31;
    int b = m >> 11, t = m & 2047;

    const float* base = g_QKV + (size_t)m * N3;
    float2 q = *(const float2*)&base[h * 64 + 2 * i];
    float2 k = *(const float2*)&base[1024 + h * 64 + 2 * i];
    float2 v = *(const float2*)&base[2048 + h * 64 + 2 * i];

    float c = g_cos[t * 32 + i];
    float s = g_sin[t * 32 + i];

    float qr0 = q.x * c - q.y * s, qr1 = q.x * s + q.y * c;
    float kr0 = k.x * c - k.y * s, kr1 = k.x * s + k.y * c;

    int bh = b * 16 + h;
    size_t toff = ((size_t)bh * 64 + 2 * i) * 2048 + t;
    g_Qt[toff]        = qr0;
    g_Qt[toff + 2048] = qr1;
    g_Kt[toff]        = kr0;
    g_Kt[toff + 2048] = kr1;

    *(float2*)&g_V[((size_t)bh * 2048 + t) * 64 + 2 * i] = v;
}

// ---------------------------------------------------------------------------
// Kernel 4: flash attention. grid(16 q-tiles, 64 bh), 256 threads.
// Tiles 128q x 64kv, 8q x 4kv per thread. S and O accumulators paired
// along q -> Q and P operands load as natural LDS.64 pairs (no packs).
// P stored transposed [k][q] with a 16B-chunk XOR swizzle: both the
// strided writes and the broadcast reads are conflict-free.
// ---------------------------------------------------------------------------
#define ATTN_SMEM ((8192 + 4096 + 4096 + 8192) * 4)   /* 98304 B */

__global__ __launch_bounds__(256, 2) void attn_kernel() {
    extern __shared__ float sm[];
    float* Qs = sm;              // [d][q]  64x128 (pre-scaled by 1/8)
    float* Ks = Qs + 8192;       // [d][k]  64x64
    float* Vs = Ks + 4096;       // [k][d]  64x64
    float* Ps = Vs + 4096;       // [k][q]  64x128, 16B-chunk swizzled

    const int bh = blockIdx.y;
    const int q0 = blockIdx.x * 128;
    const int tid = threadIdx.x;
    const int tx = tid & 15;     // k / d columns (4 each)
    const int ty = tid >> 4;     // q rows (8 each)

    const float* Qb = g_Qt + (size_t)bh * 64 * 2048;
    const float* Kb = g_Kt + (size_t)bh * 64 * 2048;
    const float* Vb = g_V  + (size_t)bh * 2048 * 64;

    // load Q tile [d][q] (linear copy; fold in softmax scale 1/sqrt(64))
    #pragma unroll
    for (int it = 0; it < 8; it++) {
        int idx = tid + it * 256;          // float4 index, 0..2047
        int d = idx >> 5, qq = (idx & 31) * 4;
        float4 v = *(const float4*)&Qb[(size_t)d * 2048 + q0 + qq];
        v.x *= 0.125f; v.y *= 0.125f; v.z *= 0.125f; v.w *= 0.125f;
        *(float4*)&Qs[d * 128 + qq] = v;
    }

    float m_i[8], l_i[8];
    u64 o2[4][4];                 // [qpair][d-col]
    #pragma unroll
    for (int r = 0; r < 8; r++) { m_i[r] = -1e30f; l_i[r] = 0.f; }
    #pragma unroll
    for (int mp = 0; mp < 4; mp++)
        #pragma unroll
        for (int j = 0; j < 4; j++) o2[mp][j] = 0ULL;

    for (int kt = 0; kt < 32; kt++) {
        __syncthreads();   // previous PV reads of Ps/Vs (and Ks) complete
        #pragma unroll
        for (int it = 0; it < 4; it++) {
            int idx = tid + it * 256;
            int d = idx >> 4, kq = (idx & 15) * 4;
            *(float4*)&Ks[d * 64 + kq] =
                *(const float4*)&Kb[(size_t)d * 2048 + kt * 64 + kq];
            *(float4*)&Vs[idx * 4] =
                *(const float4*)&Vb[(size_t)kt * 4096 + idx * 4];
        }
        __syncthreads();

        // ---- S = (Q*scale)^T K, paired along q ----
        u64 s2[4][4];
        #pragma unroll
        for (int mp = 0; mp < 4; mp++)
            #pragma unroll
            for (int j = 0; j < 4; j++) s2[mp][j] = 0ULL;

        #pragma unroll 4
        for (int d = 0; d < 64; d++) {
            const float* qrow = &Qs[d * 128 + 8 * ty];
            u64 q01 = *(const u64*)(qrow);
            u64 q23 = *(const u64*)(qrow + 2);
            u64 q45 = *(const u64*)(qrow + 4);
            u64 q67 = *(const u64*)(qrow + 6);
            float4 kv = *(const float4*)&Ks[d * 64 + 4 * tx];
            u64 k0 = pack2(kv.x, kv.x);
            u64 k1 = pack2(kv.y, kv.y);
            u64 k2 = pack2(kv.z, kv.z);
            u64 k3 = pack2(kv.w, kv.w);
            s2[0][0] = fma2(q01, k0, s2[0][0]); s2[0][1] = fma2(q01, k1, s2[0][1]);
            s2[0][2] = fma2(q01, k2, s2[0][2]); s2[0][3] = fma2(q01, k3, s2[0][3]);
            s2[1][0] = fma2(q23, k0, s2[1][0]); s2[1][1] = fma2(q23, k1, s2[1][1]);
            s2[1][2] = fma2(q23, k2, s2[1][2]); s2[1][3] = fma2(q23, k3, s2[1][3]);
            s2[2][0] = fma2(q45, k0, s2[2][0]); s2[2][1] = fma2(q45, k1, s2[2][1]);
            s2[2][2] = fma2(q45, k2, s2[2][2]); s2[2][3] = fma2(q45, k3, s2[2][3]);
            s2[3][0] = fma2(q67, k0, s2[3][0]); s2[3][1] = fma2(q67, k1, s2[3][1]);
            s2[3][2] = fma2(q67, k2, s2[3][2]); s2[3][3] = fma2(q67, k3, s2[3][3]);
        }

        // ---- online softmax (rows spread across the 16 tx lanes) ----
        float s[8][4];
        #pragma unroll
        for (int mp = 0; mp < 4; mp++)
            #pragma unroll
            for (int j = 0; j < 4; j++) {
                float2 u = unpack2(s2[mp][j]);
                s[2 * mp][j] = u.x; s[2 * mp + 1][j] = u.y;
            }

        float alpha[8];
        #pragma unroll
        for (int r = 0; r < 8; r++) {
            float mx = fmaxf(fmaxf(s[r][0], s[r][1]), fmaxf(s[r][2], s[r][3]));
            #pragma unroll
            for (int off = 1; off < 16; off <<= 1)
                mx = fmaxf(mx, __shfl_xor_sync(0xffffffffu, mx, off));
            float mnew = fmaxf(m_i[r], mx);
            alpha[r] = __expf(m_i[r] - mnew);
            float rsum = 0.f;
            #pragma unroll
            for (int j = 0; j < 4; j++) {
                s[r][j] = __expf(s[r][j] - mnew);
                rsum += s[r][j];
            }
            #pragma unroll
            for (int off = 1; off < 16; off <<= 1)
                rsum += __shfl_xor_sync(0xffffffffu, rsum, off);
            l_i[r] = l_i[r] * alpha[r] + rsum;
            m_i[r] = mnew;
        }
        #pragma unroll
        for (int mp = 0; mp < 4; mp++) {
            u64 al2 = pack2(alpha[2 * mp], alpha[2 * mp + 1]);
            #pragma unroll
            for (int j = 0; j < 4; j++) o2[mp][j] = mul2(o2[mp][j], al2);
        }

        // ---- write P transposed [k][q], XOR-swizzled 16B chunks ----
        #pragma unroll
        for (int j = 0; j < 4; j++) {
            int k = 4 * tx + j;
            int x = (k >> 1) & 7;
            int cA = ((2 * ty) ^ x) << 2;       // chunk for rows 0..3
            float* prow = &Ps[k * 128];
            *(float4*)(prow + cA) =
                make_float4(s[0][j], s[1][j], s[2][j], s[3][j]);
            *(float4*)(prow + (cA ^ 4)) =
                make_float4(s[4][j], s[5][j], s[6][j], s[7][j]);
        }
        __syncthreads();

        // ---- O += P V, paired along q ----
        #pragma unroll 4
        for (int k = 0; k < 64; k++) {
            int x = (k >> 1) & 7;
            int cA = ((2 * ty) ^ x) << 2;
            const float* prow = &Ps[k * 128];
            u64 p01 = *(const u64*)(prow + cA);
            u64 p23 = *(const u64*)(prow + cA + 2);
            u64 p45 = *(const u64*)(prow + (cA ^ 4));
            u64 p67 = *(const u64*)(prow + (cA ^ 4) + 2);
            float4 vv = *(const float4*)&Vs[k * 64 + 4 * tx];
            u64 v0 = pack2(vv.x, vv.x);
            u64 v1 = pack2(vv.y, vv.y);
            u64 v2 = pack2(vv.z, vv.z);
            u64 v3 = pack2(vv.w, vv.w);
            o2[0][0] = fma2(p01, v0, o2[0][0]); o2[0][1] = fma2(p01, v1, o2[0][1]);
            o2[0][2] = fma2(p01, v2, o2[0][2]); o2[0][3] = fma2(p01, v3, o2[0][3]);
            o2[1][0] = fma2(p23, v0, o2[1][0]); o2[1][1] = fma2(p23, v1, o2[1][1]);
            o2[1][2] = fma2(p23, v2, o2[1][2]); o2[1][3] = fma2(p23, v3, o2[1][3]);
            o2[2][0] = fma2(p45, v0, o2[2][0]); o2[2][1] = fma2(p45, v1, o2[2][1]);
            o2[2][2] = fma2(p45, v2, o2[2][2]); o2[2][3] = fma2(p45, v3, o2[2][3]);
            o2[3][0] = fma2(p67, v0, o2[3][0]); o2[3][1] = fma2(p67, v1, o2[3][1]);
            o2[3][2] = fma2(p67, v2, o2[3][2]); o2[3][3] = fma2(p67, v3, o2[3][3]);
        }
    }

    // epilogue: O /= l, write to g_A[b*T+t][h*64+d]
    const int b = bh >> 4, h = bh & 15;
    #pragma unroll
    for (int mp = 0; mp < 4; mp++) {
        float2 u0 = unpack2(o2[mp][0]);
        float2 u1 = unpack2(o2[mp][1]);
        float2 u2 = unpack2(o2[mp][2]);
        float2 u3 = unpack2(o2[mp][3]);
        float inv0 = 1.0f / l_i[2 * mp];
        float inv1 = 1.0f / l_i[2 * mp + 1];
        size_t r0 = ((size_t)(b * 2048 + q0 + 8 * ty + 2 * mp)) * 1024 + h * 64 + 4 * tx;
        *(float4*)&g_A[r0] =
            make_float4(u0.x * inv0, u1.x * inv0, u2.x * inv0, u3.x * inv0);
        *(float4*)&g_A[r0 + 1024] =
            make_float4(u0.y * inv1, u1.y * inv1, u2.y * inv1, u3.y * inv1);
    }
}

// ---------------------------------------------------------------------------
// Launcher
// ---------------------------------------------------------------------------
extern "C" void kernel_launch(void* const* d_in, const int* in_sizes, int n_in,
                              void* d_out, int out_size) {
    (void)in_sizes; (void)n_in; (void)out_size;
    const float* query = (const float*)d_in[0];
    const float* w_in  = (const float*)d_in[1];
    const float* b_in  = (const float*)d_in[2];
    const float* w_out = (const float*)d_in[3];
    const float* b_out = (const float*)d_in[4];
    float* out = (float*)d_out;

    void* pQKV = nullptr; void* pA = nullptr;
    cudaGetSymbolAddress(&pQKV, g_QKV);
    cudaGetSymbolAddress(&pA,   g_A);
    cudaFuncSetAttribute(attn_kernel,
                         cudaFuncAttributeMaxDynamicSharedMemorySize, ATTN_SMEM);

    rope_table_kernel<<<(TT * 32 + 255) / 256, 256>>>();

    gemm_bias_kernel<<<dim3(N3 / 128, MM / 128), 256>>>(
        query, w_in, b_in, (float*)pQKV, N3);

    rope_scatter_kernel<<<(MM * 512) / 256, 256>>>();

    attn_kernel<<<dim3(TT / 128, NBH), 256, ATTN_SMEM>>>();

    gemm_bias_kernel<<<dim3(DD / 128, MM / 128), 256>>>(
        (const float*)pA, w_out, b_out, out, DD);
}